// round 2
// baseline (speedup 1.0000x reference)
#include <cuda_runtime.h>
#include <cuda_bf16.h>
#include <mma.h>
#include <cstdint>
#include <cstddef>

using namespace nvcuda;

// Problem dims
#define BSZ 32
#define SSZ 512
#define FSZ 512
#define HSZ 1024
#define NC  4096   // 4 gates * H, interleaved as c = j*4 + g  (g: 0=i,1=f,2=g,3=o)

constexpr int HF = HSZ * FSZ;   // 524288
constexpr int HH = HSZ * HSZ;   // 1048576

// ---------------- device scratch (static, no allocations) ----------------
__device__ float          g_partials[256];                 // 8 matrices x 32 block partials
__device__ float          g_scalars[8];                    // [0..3] alpha_x (i,f,g,o), [4..7] alpha_h
__device__ float          g_bias[NC];                      // combined binarized bias, interleaved
__device__ __nv_bfloat16  g_wx[(size_t)NC * FSZ];          // sign(Wx), [c][k], bf16 +-1
__device__ __nv_bfloat16  g_wh[(size_t)NC * HSZ];          // sign(Wh), [c][k], bf16 +-1
__device__ __nv_bfloat16  g_xhi[(size_t)BSZ * SSZ * FSZ];  // x hi part
__device__ __nv_bfloat16  g_xlo[(size_t)BSZ * SSZ * FSZ];  // x lo part
__device__ float          g_xproj[(size_t)SSZ * BSZ * NC]; // precomputed x-part incl. alpha & bias (256MB)
__device__ __nv_bfloat16  g_hhi[2 * BSZ * HSZ];            // double-buffered h hi
__device__ __nv_bfloat16  g_hlo[2 * BSZ * HSZ];            // double-buffered h lo
__device__ unsigned       g_bar;                           // grid barrier counter (reset by finalize)

struct Ptrs {
    const float *x, *h0, *c0,
        *wii, *whi, *bii, *bhi,
        *wif, *whf, *bif, *bhf,
        *wio, *who, *bio, *bho,
        *wig, *whg, *big, *bhg;
};

__device__ __forceinline__ float sgnf(float v) {
    return (v > 0.f) ? 1.f : ((v < 0.f) ? -1.f : 0.f);
}

__device__ __forceinline__ uint4 ldg_cg_v4(const uint4* p) {
    uint4 v;
    asm volatile("ld.global.cg.v4.u32 {%0,%1,%2,%3}, [%4];"
                 : "=r"(v.x), "=r"(v.y), "=r"(v.z), "=r"(v.w) : "l"(p));
    return v;
}

// ---------------- setup kernels ----------------

// Partial sums of |W| for the 8 weight matrices. Deterministic (fixed tree).
__global__ void k_reduce(Ptrs P) {
    const float* ws[8] = {P.wii, P.whi, P.wif, P.whf, P.wio, P.who, P.wig, P.whg};
    const int    szs[8] = {HF, HH, HF, HH, HF, HH, HF, HH};
    int m = blockIdx.x >> 5, sl = blockIdx.x & 31;
    int per = szs[m] / 32;
    const float* w = ws[m] + (size_t)sl * per;
    float s = 0.f;
    for (int i = threadIdx.x; i < per; i += 256) s += fabsf(w[i]);
    __shared__ float red[256];
    red[threadIdx.x] = s;
    __syncthreads();
    for (int o = 128; o > 0; o >>= 1) {
        if (threadIdx.x < o) red[threadIdx.x] += red[threadIdx.x + o];
        __syncthreads();
    }
    if (threadIdx.x == 0) g_partials[m * 32 + sl] = red[0];
}

// alphas, combined biases, barrier reset
__global__ void k_finalize(Ptrs P) {
    int tid = threadIdx.x;
    __shared__ float red[256];
    __shared__ float aw[8], ab[8];
    const int szs[8] = {HF, HH, HF, HH, HF, HH, HF, HH};
    if (tid < 8) {
        float s = 0.f;
        for (int i = 0; i < 32; i++) s += g_partials[tid * 32 + i];
        aw[tid] = s / (float)szs[tid];
    }
    const float* bs[8] = {P.bii, P.bhi, P.bif, P.bhf, P.bio, P.bho, P.big, P.bhg};
    for (int v = 0; v < 8; v++) {
        float s = 0.f;
        for (int i = tid; i < HSZ; i += 256) s += fabsf(bs[v][i]);
        red[tid] = s;
        __syncthreads();
        for (int o = 128; o > 0; o >>= 1) {
            if (tid < o) red[tid] += red[tid + o];
            __syncthreads();
        }
        if (tid == 0) ab[v] = red[0] / (float)HSZ;
        __syncthreads();
    }
    // gate order i,f,g,o:  input matrices {wii,wif,wig,wio} = aw{0,2,6,4}; hidden = aw{1,3,7,5}
    if (tid < 4) {
        const int mx[4] = {0, 2, 6, 4};
        const int mh[4] = {1, 3, 7, 5};
        g_scalars[tid]     = aw[mx[tid]];
        g_scalars[4 + tid] = aw[mh[tid]];
    }
    __syncthreads();
    const float* bx[4] = {P.bii, P.bif, P.big, P.bio};
    const float* bh[4] = {P.bhi, P.bhf, P.bhg, P.bho};
    float abx[4] = {ab[0], ab[2], ab[6], ab[4]};
    float abh[4] = {ab[1], ab[3], ab[7], ab[5]};
    for (int c = tid; c < NC; c += 256) {
        int j = c >> 2, g = c & 3;
        g_bias[c] = abx[g] * sgnf(bx[g][j]) + abh[g] * sgnf(bh[g][j]);
    }
    if (tid == 0) g_bar = 0u;   // reset grid barrier for the recurrent kernel
}

// write sign(W) as bf16 +-1, interleaved gate layout c = j*4+g
__global__ void k_binarize(Ptrs P) {
    const float* wx[4] = {P.wii, P.wif, P.wig, P.wio};
    const float* wh[4] = {P.whi, P.whf, P.whg, P.who};
    int idx = blockIdx.x * 256 + threadIdx.x;
    if (idx < NC * FSZ) {
        int c = idx >> 9, k = idx & 511;
        int j = c >> 2, g = c & 3;
        g_wx[idx] = __float2bfloat16(sgnf(wx[g][(size_t)j * FSZ + k]));
    } else {
        int r = idx - NC * FSZ;
        if (r < NC * HSZ) {
            int c = r >> 10, k = r & 1023;
            int j = c >> 2, g = c & 3;
            g_wh[r] = __float2bfloat16(sgnf(wh[g][(size_t)j * HSZ + k]));
        }
    }
}

// split inputs into bf16 hi/lo (exact-sum decomposition)
__global__ void k_convx(Ptrs P) {
    int idx = blockIdx.x * 256 + threadIdx.x;
    if (idx < BSZ * SSZ * FSZ) {
        float v = P.x[idx];
        __nv_bfloat16 hi = __float2bfloat16(v);
        g_xhi[idx] = hi;
        g_xlo[idx] = __float2bfloat16(v - __bfloat162float(hi));
    }
}

__global__ void k_inith(Ptrs P) {
    int idx = blockIdx.x * 256 + threadIdx.x;
    if (idx < BSZ * HSZ) {
        float v = P.h0[idx];
        __nv_bfloat16 hi = __float2bfloat16(v);
        g_hhi[idx] = hi;                                        // buffer parity 0
        g_hlo[idx] = __float2bfloat16(v - __bfloat162float(hi));
    }
}

// ---------------- input projection GEMM ----------------
// Xproj[t][b][c] = alpha_x[g] * sum_k sign(Wx)[c][k] * x[b][t][k] + bias[c]
// Block: 32 rows x 128 cols, K=512, hi/lo -> 2 MMAs per k-chunk.
__global__ void __launch_bounds__(256) k_xproj() {
    extern __shared__ unsigned char smem[];
    __nv_bfloat16* sb = (__nv_bfloat16*)smem;   // 128 cols x 512 k  (128KB)
    int tid = threadIdx.x;
    int c0 = blockIdx.x * 128, row0 = blockIdx.y * 32;

    {   // stage Wx tile (contiguous rows)
        const uint4* src = (const uint4*)(g_wx + (size_t)c0 * FSZ);
        uint4* dst = (uint4*)sb;
        for (int i = tid; i < 8192; i += 256) dst[i] = src[i];
    }
    __syncthreads();

    int wid = tid >> 5;
    int tr = wid & 1, tcp = wid >> 1;   // 2 row tiles x (4 warp-pairs of 2 col tiles)

    wmma::fragment<wmma::accumulator, 16, 16, 16, float> cf[2];
    wmma::fill_fragment(cf[0], 0.f);
    wmma::fill_fragment(cf[1], 0.f);
    wmma::fragment<wmma::matrix_a, 16, 16, 16, __nv_bfloat16, wmma::row_major> ahi, alo;
    wmma::fragment<wmma::matrix_b, 16, 16, 16, __nv_bfloat16, wmma::col_major> bf;

    const __nv_bfloat16* Ahi = g_xhi + (size_t)(row0 + tr * 16) * FSZ;
    const __nv_bfloat16* Alo = g_xlo + (size_t)(row0 + tr * 16) * FSZ;

    for (int k = 0; k < FSZ; k += 16) {
        wmma::load_matrix_sync(ahi, Ahi + k, FSZ);
        wmma::load_matrix_sync(alo, Alo + k, FSZ);
#pragma unroll
        for (int j = 0; j < 2; j++) {
            int tc = tcp * 2 + j;
            wmma::load_matrix_sync(bf, sb + (size_t)(tc * 16) * FSZ + k, FSZ);
            wmma::mma_sync(cf[j], ahi, bf, cf[j]);
            wmma::mma_sync(cf[j], alo, bf, cf[j]);
        }
    }
    __syncthreads();
    float* scf = (float*)smem;   // 32 x 128 f32 (aliases weight stage; done with it)
#pragma unroll
    for (int j = 0; j < 2; j++) {
        int tc = tcp * 2 + j;
        wmma::store_matrix_sync(scf + (tr * 16) * 128 + tc * 16, cf[j], 128, wmma::mem_row_major);
    }
    __syncthreads();

    float ax[4] = {g_scalars[0], g_scalars[1], g_scalars[2], g_scalars[3]};
    for (int i = tid; i < 4096; i += 256) {
        int rl = i >> 7, cl = i & 127;
        int r = row0 + rl;
        int b = r >> 9, t = r & 511;
        int c = c0 + cl, g = cl & 3;
        g_xproj[((size_t)t * BSZ + b) * NC + c] = ax[g] * scf[i] + g_bias[c];
    }
}

// ---------------- persistent recurrent kernel ----------------
// 128 blocks, block bid owns j in [bid*8, bid*8+8) across all 4 gates (32 cols).
// Wh signs resident in smem for all 512 steps; h staged via ld.global.cg (L2-coherent).
// Grid barrier is BOUNDED: a co-residency failure degrades to a wrong answer
// (diagnosable) instead of a GPU hang (container kill).
__global__ void __launch_bounds__(256, 1) k_recur(const float* __restrict__ c0in,
                                                  float* __restrict__ out) {
    extern __shared__ unsigned char smem[];
    __nv_bfloat16* sw  = (__nv_bfloat16*)smem;             // 32 x 1024 weights (64KB)
    __nv_bfloat16* shh = (__nv_bfloat16*)(smem + 65536);   // 32 x 1024 h hi (64KB)
    __nv_bfloat16* shl = (__nv_bfloat16*)(smem + 131072);  // 32 x 1024 h lo (64KB)
    float*         sc  = (float*)(smem + 196608);          // [2][32][32] f32 partials (8KB)

    int tid = threadIdx.x, bid = blockIdx.x;
    int ccol = bid * 32;

    {   // stage this block's Wh sign columns (contiguous) once
        const uint4* src = (const uint4*)(g_wh + (size_t)ccol * HSZ);
        uint4* dst = (uint4*)sw;
        for (int i = tid; i < 4096; i += 256) dst[i] = src[i];
    }
    float ah[4] = {g_scalars[4], g_scalars[5], g_scalars[6], g_scalars[7]};

    int b = tid >> 3, jl = tid & 7;          // thread owns (batch b, local j)
    int jg = bid * 8 + jl;
    float creg = c0in[b * HSZ + jg];         // c lives in a register forever

    int wid = tid >> 5;
    int ks = wid & 1, tile = wid >> 1;       // 2-way K split, 2x2 (16x16) C tiles
    int tr = tile & 1, tc = tile >> 1;

    float* outh = out + (size_t)BSZ * SSZ * HSZ;
    float* outc = outh + BSZ * HSZ;

    int p = 0;
    for (int t = 0; t < SSZ; t++) {
        // prefetch this step's xproj early; consumed only in the epilogue
        float4 xp = *(const float4*)(g_xproj + ((size_t)t * BSZ + b) * NC + ccol + jl * 4);

        __syncthreads();   // smem free; weights staged (t==0)
        {   // stage h hi/lo (parity p) bypassing L1
            const uint4* s1 = (const uint4*)(g_hhi + p * (BSZ * HSZ));
            const uint4* s2 = (const uint4*)(g_hlo + p * (BSZ * HSZ));
            uint4* d1 = (uint4*)shh;
            uint4* d2 = (uint4*)shl;
            for (int i = tid; i < 4096; i += 256) {
                d1[i] = ldg_cg_v4(s1 + i);
                d2[i] = ldg_cg_v4(s2 + i);
            }
        }
        __syncthreads();

        wmma::fragment<wmma::accumulator, 16, 16, 16, float> cf;
        wmma::fill_fragment(cf, 0.f);
        wmma::fragment<wmma::matrix_a, 16, 16, 16, __nv_bfloat16, wmma::row_major> ahi, alo;
        wmma::fragment<wmma::matrix_b, 16, 16, 16, __nv_bfloat16, wmma::col_major> bf;

        for (int kk = 0; kk < 512; kk += 16) {
            int k = ks * 512 + kk;
            wmma::load_matrix_sync(ahi, shh + (size_t)(tr * 16) * HSZ + k, HSZ);
            wmma::load_matrix_sync(alo, shl + (size_t)(tr * 16) * HSZ + k, HSZ);
            wmma::load_matrix_sync(bf, sw + (size_t)(tc * 16) * HSZ + k, HSZ);
            wmma::mma_sync(cf, ahi, bf, cf);
            wmma::mma_sync(cf, alo, bf, cf);
        }
        wmma::store_matrix_sync(sc + ks * 1024 + (tr * 16) * 32 + tc * 16, cf, 32,
                                wmma::mem_row_major);
        __syncthreads();

        // ---- epilogue: one thread per (b, j) ----
        int ci = b * 32 + jl * 4;
        float pi = xp.x + ah[0] * (sc[ci + 0] + sc[1024 + ci + 0]);
        float pf = xp.y + ah[1] * (sc[ci + 1] + sc[1024 + ci + 1]);
        float pg = xp.z + ah[2] * (sc[ci + 2] + sc[1024 + ci + 2]);
        float po = xp.w + ah[3] * (sc[ci + 3] + sc[1024 + ci + 3]);
        float gi = 1.f / (1.f + expf(-pi));
        float gf = 1.f / (1.f + expf(-pf));
        float gg = tanhf(pg);
        float go = 1.f / (1.f + expf(-po));
        creg = gf * creg + gi * gg;
        float h2 = go * tanhf(creg);

        out[((size_t)b * SSZ + t) * HSZ + jg] = h2;
        int np = p ^ 1;
        __nv_bfloat16 hi = __float2bfloat16(h2);
        g_hhi[np * (BSZ * HSZ) + b * HSZ + jg] = hi;
        g_hlo[np * (BSZ * HSZ) + b * HSZ + jg] =
            __float2bfloat16(h2 - __bfloat162float(hi));
        if (t == SSZ - 1) {
            outh[b * HSZ + jg] = h2;
            outc[b * HSZ + jg] = creg;
        }

        // ---- bounded grid barrier (publishes h writes for next step) ----
        __threadfence();
        __syncthreads();
        if (tid == 0) {
            atomicAdd(&g_bar, 1u);
            unsigned target = (unsigned)(t + 1) * gridDim.x;
            const volatile unsigned* vb = &g_bar;
            unsigned spins = 0;
            while (*vb < target) {
                __nanosleep(32);
                if (++spins > (1u << 21)) break;   // ~60ms cap: deadlock -> wrong answer, not hang
            }
            __threadfence();
        }
        __syncthreads();
        p = np;
    }
}

// ---------------- launcher ----------------
extern "C" void kernel_launch(void* const* d_in, const int* in_sizes, int n_in,
                              void* d_out, int out_size) {
    Ptrs P;
    P.x   = (const float*)d_in[0];
    P.h0  = (const float*)d_in[1];
    P.c0  = (const float*)d_in[2];
    P.wii = (const float*)d_in[3];  P.whi = (const float*)d_in[4];
    P.bii = (const float*)d_in[5];  P.bhi = (const float*)d_in[6];
    P.wif = (const float*)d_in[7];  P.whf = (const float*)d_in[8];
    P.bif = (const float*)d_in[9];  P.bhf = (const float*)d_in[10];
    P.wio = (const float*)d_in[11]; P.who = (const float*)d_in[12];
    P.bio = (const float*)d_in[13]; P.bho = (const float*)d_in[14];
    P.wig = (const float*)d_in[15]; P.whg = (const float*)d_in[16];
    P.big = (const float*)d_in[17]; P.bhg = (const float*)d_in[18];

    cudaFuncSetAttribute(k_xproj, cudaFuncAttributeMaxDynamicSharedMemorySize, 131072);
    cudaFuncSetAttribute(k_recur, cudaFuncAttributeMaxDynamicSharedMemorySize, 204800);

    k_reduce<<<256, 256>>>(P);
    k_finalize<<<1, 256>>>(P);
    k_binarize<<<24576, 256>>>(P);
    k_convx<<<32768, 256>>>(P);
    k_inith<<<128, 256>>>(P);
    k_xproj<<<dim3(32, 512), 256, 131072>>>();
    k_recur<<<128, 256, 204800>>>((const float*)d_in[2], (float*)d_out);
}

// round 3
// speedup vs baseline: 2.2790x; 2.2790x over previous
#include <cuda_runtime.h>
#include <cuda_bf16.h>
#include <mma.h>
#include <cstdint>
#include <cstddef>

using namespace nvcuda;

// Problem dims
#define BSZ 32
#define SSZ 512
#define FSZ 512
#define HSZ 1024
#define NC  4096   // 4 gates * H, interleaved as c = j*4 + g  (g: 0=i,1=f,2=g,3=o)

constexpr int HF = HSZ * FSZ;   // 524288
constexpr int HH = HSZ * HSZ;   // 1048576

// Padded smem strides (elements). Chosen so row_stride_bytes mod 128 == 16
// -> 8 consecutive rows occupy 8 distinct 16B slots -> conflict-free LDSM.
#define SWP  1032   // for K=1024 rows (2064 B)
#define XBP  520    // for K=512 rows  (1040 B)
#define SCP  36     // f32 partial tile stride (144 B)

// ---------------- device scratch (static, no allocations) ----------------
__device__ float          g_partials[256];
__device__ float          g_scalars[8];                    // [0..3] alpha_x, [4..7] alpha_h (i,f,g,o)
__device__ float          g_bias[NC];
__device__ __nv_bfloat16  g_wx[(size_t)NC * FSZ];          // sign(Wx), [c][k]
__device__ __nv_bfloat16  g_wh[(size_t)NC * HSZ];          // sign(Wh), [c][k]
__device__ __nv_bfloat16  g_xhi[(size_t)BSZ * SSZ * FSZ];
__device__ __nv_bfloat16  g_xlo[(size_t)BSZ * SSZ * FSZ];
__device__ float          g_xproj[(size_t)SSZ * BSZ * NC]; // x-part incl. alpha & bias
__device__ __nv_bfloat16  g_hhi[2 * BSZ * HSZ];
__device__ __nv_bfloat16  g_hlo[2 * BSZ * HSZ];
__device__ unsigned       g_bar;

struct Ptrs {
    const float *x, *h0, *c0,
        *wii, *whi, *bii, *bhi,
        *wif, *whf, *bif, *bhf,
        *wio, *who, *bio, *bho,
        *wig, *whg, *big, *bhg;
};

__device__ __forceinline__ float sgnf(float v) {
    return (v > 0.f) ? 1.f : ((v < 0.f) ? -1.f : 0.f);
}

__device__ __forceinline__ void cp16(void* s, const void* g) {
    uint32_t sa = (uint32_t)__cvta_generic_to_shared(s);
    asm volatile("cp.async.cg.shared.global [%0], [%1], 16;" :: "r"(sa), "l"(g));
}
__device__ __forceinline__ void cp_commit_wait0() {
    asm volatile("cp.async.commit_group;");
    asm volatile("cp.async.wait_group 0;");
}

// ---------------- setup kernels ----------------
__global__ void k_reduce(Ptrs P) {
    const float* ws[8] = {P.wii, P.whi, P.wif, P.whf, P.wio, P.who, P.wig, P.whg};
    const int    szs[8] = {HF, HH, HF, HH, HF, HH, HF, HH};
    int m = blockIdx.x >> 5, sl = blockIdx.x & 31;
    int per = szs[m] / 32;
    const float* w = ws[m] + (size_t)sl * per;
    float s = 0.f;
    for (int i = threadIdx.x; i < per; i += 256) s += fabsf(w[i]);
    __shared__ float red[256];
    red[threadIdx.x] = s;
    __syncthreads();
    for (int o = 128; o > 0; o >>= 1) {
        if (threadIdx.x < o) red[threadIdx.x] += red[threadIdx.x + o];
        __syncthreads();
    }
    if (threadIdx.x == 0) g_partials[m * 32 + sl] = red[0];
}

__global__ void k_finalize(Ptrs P) {
    int tid = threadIdx.x;
    __shared__ float red[256];
    __shared__ float aw[8], ab[8];
    const int szs[8] = {HF, HH, HF, HH, HF, HH, HF, HH};
    if (tid < 8) {
        float s = 0.f;
        for (int i = 0; i < 32; i++) s += g_partials[tid * 32 + i];
        aw[tid] = s / (float)szs[tid];
    }
    const float* bs[8] = {P.bii, P.bhi, P.bif, P.bhf, P.bio, P.bho, P.big, P.bhg};
    for (int v = 0; v < 8; v++) {
        float s = 0.f;
        for (int i = tid; i < HSZ; i += 256) s += fabsf(bs[v][i]);
        red[tid] = s;
        __syncthreads();
        for (int o = 128; o > 0; o >>= 1) {
            if (tid < o) red[tid] += red[tid + o];
            __syncthreads();
        }
        if (tid == 0) ab[v] = red[0] / (float)HSZ;
        __syncthreads();
    }
    if (tid < 4) {
        const int mx[4] = {0, 2, 6, 4};
        const int mh[4] = {1, 3, 7, 5};
        g_scalars[tid]     = aw[mx[tid]];
        g_scalars[4 + tid] = aw[mh[tid]];
    }
    __syncthreads();
    const float* bx[4] = {P.bii, P.bif, P.big, P.bio};
    const float* bh[4] = {P.bhi, P.bhf, P.bhg, P.bho};
    float abx[4] = {ab[0], ab[2], ab[6], ab[4]};
    float abh[4] = {ab[1], ab[3], ab[7], ab[5]};
    for (int c = tid; c < NC; c += 256) {
        int j = c >> 2, g = c & 3;
        g_bias[c] = abx[g] * sgnf(bx[g][j]) + abh[g] * sgnf(bh[g][j]);
    }
    if (tid == 0) g_bar = 0u;
}

__global__ void k_binarize(Ptrs P) {
    const float* wx[4] = {P.wii, P.wif, P.wig, P.wio};
    const float* wh[4] = {P.whi, P.whf, P.whg, P.who};
    int idx = blockIdx.x * 256 + threadIdx.x;
    if (idx < NC * FSZ) {
        int c = idx >> 9, k = idx & 511;
        int j = c >> 2, g = c & 3;
        g_wx[idx] = __float2bfloat16(sgnf(wx[g][(size_t)j * FSZ + k]));
    } else {
        int r = idx - NC * FSZ;
        if (r < NC * HSZ) {
            int c = r >> 10, k = r & 1023;
            int j = c >> 2, g = c & 3;
            g_wh[r] = __float2bfloat16(sgnf(wh[g][(size_t)j * HSZ + k]));
        }
    }
}

__global__ void k_convx(Ptrs P) {
    int idx = blockIdx.x * 256 + threadIdx.x;
    if (idx < BSZ * SSZ * FSZ) {
        float v = P.x[idx];
        __nv_bfloat16 hi = __float2bfloat16(v);
        g_xhi[idx] = hi;
        g_xlo[idx] = __float2bfloat16(v - __bfloat162float(hi));
    }
}

__global__ void k_inith(Ptrs P) {
    int idx = blockIdx.x * 256 + threadIdx.x;
    if (idx < BSZ * HSZ) {
        float v = P.h0[idx];
        __nv_bfloat16 hi = __float2bfloat16(v);
        g_hhi[idx] = hi;
        g_hlo[idx] = __float2bfloat16(v - __bfloat162float(hi));
    }
}

// ---------------- input projection GEMM ----------------
// Block: 32 rows x 128 cols, K=512. A (hi/lo) and B staged in padded smem.
__global__ void __launch_bounds__(256) k_xproj() {
    extern __shared__ unsigned char smem[];
    __nv_bfloat16* sb = (__nv_bfloat16*)smem;                       // 128 x XBP  (133,120 B)
    __nv_bfloat16* sa = (__nv_bfloat16*)(smem + 133120);            // 2 x 32 x XBP (66,560 B)
    int tid = threadIdx.x;
    int c0 = blockIdx.x * 128, row0 = blockIdx.y * 32;

    {   // stage Wx tile into padded layout (64 uint4 per 512-elem row)
        const uint4* src = (const uint4*)(g_wx + (size_t)c0 * FSZ);
        for (int i = tid; i < 8192; i += 256) {
            int r = i >> 6, cgrp = i & 63;
            *(uint4*)((unsigned char*)sb + r * (XBP * 2) + cgrp * 16) = src[i];
        }
        // stage A hi and lo
        const uint4* shi = (const uint4*)(g_xhi + (size_t)row0 * FSZ);
        const uint4* slo = (const uint4*)(g_xlo + (size_t)row0 * FSZ);
        for (int i = tid; i < 2048; i += 256) {
            int r = i >> 6, cgrp = i & 63;
            *(uint4*)((unsigned char*)sa + r * (XBP * 2) + cgrp * 16) = shi[i];
            *(uint4*)((unsigned char*)sa + (32 + r) * (XBP * 2) + cgrp * 16) = slo[i];
        }
    }
    __syncthreads();

    int wid = tid >> 5;
    int tr = wid & 1, tcp = wid >> 1;

    wmma::fragment<wmma::accumulator, 16, 16, 16, float> cf[2];
    wmma::fill_fragment(cf[0], 0.f);
    wmma::fill_fragment(cf[1], 0.f);
    wmma::fragment<wmma::matrix_a, 16, 16, 16, __nv_bfloat16, wmma::row_major> ahi, alo;
    wmma::fragment<wmma::matrix_b, 16, 16, 16, __nv_bfloat16, wmma::col_major> bf;

    const __nv_bfloat16* Ahi = sa + (size_t)(tr * 16) * XBP;
    const __nv_bfloat16* Alo = sa + (size_t)(32 + tr * 16) * XBP;

#pragma unroll 4
    for (int k = 0; k < FSZ; k += 16) {
        wmma::load_matrix_sync(ahi, Ahi + k, XBP);
        wmma::load_matrix_sync(alo, Alo + k, XBP);
#pragma unroll
        for (int j = 0; j < 2; j++) {
            int tc = tcp * 2 + j;
            wmma::load_matrix_sync(bf, sb + (size_t)(tc * 16) * XBP + k, XBP);
            wmma::mma_sync(cf[j], ahi, bf, cf[j]);
            wmma::mma_sync(cf[j], alo, bf, cf[j]);
        }
    }
    __syncthreads();
    float* scf = (float*)smem;   // 32 x 132 f32 (aliases B stage; done with it)
#pragma unroll
    for (int j = 0; j < 2; j++) {
        int tc = tcp * 2 + j;
        wmma::store_matrix_sync(scf + (tr * 16) * 132 + tc * 16, cf[j], 132, wmma::mem_row_major);
    }
    __syncthreads();

    float ax[4] = {g_scalars[0], g_scalars[1], g_scalars[2], g_scalars[3]};
    for (int i = tid; i < 4096; i += 256) {
        int rl = i >> 7, cl = i & 127;
        int r = row0 + rl;
        int b = r >> 9, t = r & 511;
        int c = c0 + cl, g = cl & 3;
        g_xproj[((size_t)t * BSZ + b) * NC + c] = ax[g] * scf[rl * 132 + cl] + g_bias[c];
    }
}

// ---------------- persistent recurrent kernel ----------------
__global__ void __launch_bounds__(256, 1) k_recur(const float* __restrict__ c0in,
                                                  float* __restrict__ out) {
    extern __shared__ unsigned char smem[];
    // padded layouts (row stride 2064 B)
    unsigned char* swb  = smem;                 // 32 x 2064 = 66,048 B  weights
    unsigned char* shhb = smem + 66048;         // 32 x 2064             h hi
    unsigned char* shlb = smem + 132096;        // 32 x 2064             h lo
    float*         sc   = (float*)(smem + 198144);   // 2 x 32 x SCP f32 = 9,216 B
    __nv_bfloat16* sw  = (__nv_bfloat16*)swb;
    __nv_bfloat16* shh = (__nv_bfloat16*)shhb;
    __nv_bfloat16* shl = (__nv_bfloat16*)shlb;

    int tid = threadIdx.x, bid = blockIdx.x;
    int ccol = bid * 32;

    {   // stage this block's Wh sign columns once (128 uint4 per 1024-elem row)
        const uint4* src = (const uint4*)(g_wh + (size_t)ccol * HSZ);
        for (int i = tid; i < 4096; i += 256) {
            int r = i >> 7, cgrp = i & 127;
            *(uint4*)(swb + r * 2064 + cgrp * 16) = src[i];
        }
    }
    float ah[4] = {g_scalars[4], g_scalars[5], g_scalars[6], g_scalars[7]};

    int b = tid >> 3, jl = tid & 7;
    int jg = bid * 8 + jl;
    float creg = c0in[b * HSZ + jg];

    int wid = tid >> 5;
    int ks = wid & 1, tile = wid >> 1;
    int tr = tile & 1, tc = tile >> 1;

    float* outh = out + (size_t)BSZ * SSZ * HSZ;
    float* outc = outh + BSZ * HSZ;

    int p = 0;
    for (int t = 0; t < SSZ; t++) {
        float4 xp = *(const float4*)(g_xproj + ((size_t)t * BSZ + b) * NC + ccol + jl * 4);

        __syncthreads();
        {   // stage h hi/lo via cp.async.cg (L1-bypassing, full MLP)
            const uint4* s1 = (const uint4*)(g_hhi + p * (BSZ * HSZ));
            const uint4* s2 = (const uint4*)(g_hlo + p * (BSZ * HSZ));
            for (int i = tid; i < 4096; i += 256) {
                int r = i >> 7, cgrp = i & 127;
                cp16(shhb + r * 2064 + cgrp * 16, s1 + i);
                cp16(shlb + r * 2064 + cgrp * 16, s2 + i);
            }
            cp_commit_wait0();
        }
        __syncthreads();

        wmma::fragment<wmma::accumulator, 16, 16, 16, float> cfh, cfl;
        wmma::fill_fragment(cfh, 0.f);
        wmma::fill_fragment(cfl, 0.f);
        wmma::fragment<wmma::matrix_a, 16, 16, 16, __nv_bfloat16, wmma::row_major> ahi, alo;
        wmma::fragment<wmma::matrix_b, 16, 16, 16, __nv_bfloat16, wmma::col_major> bf;

#pragma unroll 4
        for (int kk = 0; kk < 512; kk += 16) {
            int k = ks * 512 + kk;
            wmma::load_matrix_sync(ahi, shh + (size_t)(tr * 16) * SWP + k, SWP);
            wmma::load_matrix_sync(alo, shl + (size_t)(tr * 16) * SWP + k, SWP);
            wmma::load_matrix_sync(bf, sw + (size_t)(tc * 16) * SWP + k, SWP);
            wmma::mma_sync(cfh, ahi, bf, cfh);
            wmma::mma_sync(cfl, alo, bf, cfl);
        }
#pragma unroll
        for (int e = 0; e < cfh.num_elements; e++) cfh.x[e] += cfl.x[e];
        wmma::store_matrix_sync(sc + ks * (32 * SCP) + (tr * 16) * SCP + tc * 16, cfh, SCP,
                                wmma::mem_row_major);
        __syncthreads();

        // ---- epilogue: one thread per (b, j) ----
        int ci = b * SCP + jl * 4;
        int o2 = 32 * SCP;
        float pi = xp.x + ah[0] * (sc[ci + 0] + sc[o2 + ci + 0]);
        float pf = xp.y + ah[1] * (sc[ci + 1] + sc[o2 + ci + 1]);
        float pg = xp.z + ah[2] * (sc[ci + 2] + sc[o2 + ci + 2]);
        float po = xp.w + ah[3] * (sc[ci + 3] + sc[o2 + ci + 3]);
        float gi = 1.f / (1.f + expf(-pi));
        float gf = 1.f / (1.f + expf(-pf));
        float gg = tanhf(pg);
        float go = 1.f / (1.f + expf(-po));
        creg = gf * creg + gi * gg;
        float h2 = go * tanhf(creg);

        out[((size_t)b * SSZ + t) * HSZ + jg] = h2;
        int np = p ^ 1;
        __nv_bfloat16 hi = __float2bfloat16(h2);
        g_hhi[np * (BSZ * HSZ) + b * HSZ + jg] = hi;
        g_hlo[np * (BSZ * HSZ) + b * HSZ + jg] =
            __float2bfloat16(h2 - __bfloat162float(hi));
        if (t == SSZ - 1) {
            outh[b * HSZ + jg] = h2;
            outc[b * HSZ + jg] = creg;
        }

        // ---- bounded grid barrier ----
        __threadfence();
        __syncthreads();
        if (tid == 0) {
            atomicAdd(&g_bar, 1u);
            unsigned target = (unsigned)(t + 1) * gridDim.x;
            const volatile unsigned* vb = &g_bar;
            unsigned spins = 0;
            while (*vb < target) {
                if (++spins > (1u << 16)) break;   // fail-slow, not hang
            }
            __threadfence();
        }
        __syncthreads();
        p = np;
    }
}

// ---------------- launcher ----------------
extern "C" void kernel_launch(void* const* d_in, const int* in_sizes, int n_in,
                              void* d_out, int out_size) {
    Ptrs P;
    P.x   = (const float*)d_in[0];
    P.h0  = (const float*)d_in[1];
    P.c0  = (const float*)d_in[2];
    P.wii = (const float*)d_in[3];  P.whi = (const float*)d_in[4];
    P.bii = (const float*)d_in[5];  P.bhi = (const float*)d_in[6];
    P.wif = (const float*)d_in[7];  P.whf = (const float*)d_in[8];
    P.bif = (const float*)d_in[9];  P.bhf = (const float*)d_in[10];
    P.wio = (const float*)d_in[11]; P.who = (const float*)d_in[12];
    P.bio = (const float*)d_in[13]; P.bho = (const float*)d_in[14];
    P.wig = (const float*)d_in[15]; P.whg = (const float*)d_in[16];
    P.big = (const float*)d_in[17]; P.bhg = (const float*)d_in[18];

    cudaFuncSetAttribute(k_xproj, cudaFuncAttributeMaxDynamicSharedMemorySize, 199680);
    cudaFuncSetAttribute(k_recur, cudaFuncAttributeMaxDynamicSharedMemorySize, 207360);

    k_reduce<<<256, 256>>>(P);
    k_finalize<<<1, 256>>>(P);
    k_binarize<<<24576, 256>>>(P);
    k_convx<<<32768, 256>>>(P);
    k_inith<<<128, 256>>>(P);
    k_xproj<<<dim3(32, 512), 256, 199680>>>();
    k_recur<<<128, 256, 207360>>>((const float*)d_in[2], (float*)d_out);
}

// round 4
// speedup vs baseline: 2.5729x; 1.1290x over previous
#include <cuda_runtime.h>
#include <cuda_bf16.h>
#include <mma.h>
#include <cstdint>
#include <cstddef>

using namespace nvcuda;

// Problem dims
#define BSZ 32
#define SSZ 512
#define FSZ 512
#define HSZ 1024
#define NC  4096   // 4 gates * H, interleaved as c = j*4 + g  (g: 0=i,1=f,2=g,3=o)

constexpr int HF = HSZ * FSZ;   // 524288
constexpr int HH = HSZ * HSZ;   // 1048576

// Padded smem strides (elements). row_stride_bytes mod 128 == 16 -> conflict-free LDSM.
#define SWP  1032   // K=1024 rows (2064 B)
#define XBP  520    // K=512 rows  (1040 B)
#define SCP  36     // f32 partial tile stride

// ---------------- device scratch (static, no allocations) ----------------
__device__ float          g_partials[256];
__device__ float          g_scalars[8];                    // [0..3] alpha_x, [4..7] alpha_h (i,f,g,o)
__device__ float          g_bias[NC];
__device__ __nv_bfloat16  g_wx[(size_t)NC * FSZ];          // sign(Wx), [c][k]
__device__ __nv_bfloat16  g_wh[(size_t)NC * HSZ];          // sign(Wh), [c][k]
__device__ __nv_bfloat16  g_xhi[(size_t)BSZ * SSZ * FSZ];
__device__ __nv_bfloat16  g_xlo[(size_t)BSZ * SSZ * FSZ];
__device__ float          g_xproj[(size_t)SSZ * BSZ * NC]; // x-part incl. alpha & bias
__device__ __nv_bfloat16  g_hhi[2 * BSZ * HSZ];
__device__ __nv_bfloat16  g_hlo[2 * BSZ * HSZ];
__device__ unsigned       g_arrive[128 * 32];              // per-block arrival flags, 128B apart

struct Ptrs {
    const float *x, *h0, *c0,
        *wii, *whi, *bii, *bhi,
        *wif, *whf, *bif, *bhf,
        *wio, *who, *bio, *bho,
        *wig, *whg, *big, *bhg;
};

__device__ __forceinline__ float sgnf(float v) {
    return (v > 0.f) ? 1.f : ((v < 0.f) ? -1.f : 0.f);
}

__device__ __forceinline__ void cp16(void* s, const void* g) {
    uint32_t sa = (uint32_t)__cvta_generic_to_shared(s);
    asm volatile("cp.async.cg.shared.global [%0], [%1], 16;" :: "r"(sa), "l"(g));
}
__device__ __forceinline__ void cp_commit() {
    asm volatile("cp.async.commit_group;");
}
__device__ __forceinline__ void cp_wait1() {
    asm volatile("cp.async.wait_group 1;");
}
__device__ __forceinline__ void cp_wait0() {
    asm volatile("cp.async.wait_group 0;");
}
__device__ __forceinline__ unsigned ld_acq(const unsigned* p) {
    unsigned v;
    asm volatile("ld.acquire.gpu.global.u32 %0, [%1];" : "=r"(v) : "l"(p));
    return v;
}
__device__ __forceinline__ void st_rel(unsigned* p, unsigned v) {
    asm volatile("st.release.gpu.global.u32 [%0], %1;" :: "l"(p), "r"(v));
}

// ---------------- setup kernels ----------------
__global__ void k_reduce(Ptrs P) {
    const float* ws[8] = {P.wii, P.whi, P.wif, P.whf, P.wio, P.who, P.wig, P.whg};
    const int    szs[8] = {HF, HH, HF, HH, HF, HH, HF, HH};
    int m = blockIdx.x >> 5, sl = blockIdx.x & 31;
    int per = szs[m] / 32;
    const float* w = ws[m] + (size_t)sl * per;
    float s = 0.f;
    for (int i = threadIdx.x; i < per; i += 256) s += fabsf(w[i]);
    __shared__ float red[256];
    red[threadIdx.x] = s;
    __syncthreads();
    for (int o = 128; o > 0; o >>= 1) {
        if (threadIdx.x < o) red[threadIdx.x] += red[threadIdx.x + o];
        __syncthreads();
    }
    if (threadIdx.x == 0) g_partials[m * 32 + sl] = red[0];
}

__global__ void k_finalize(Ptrs P) {
    int tid = threadIdx.x;
    __shared__ float red[256];
    __shared__ float aw[8], ab[8];
    const int szs[8] = {HF, HH, HF, HH, HF, HH, HF, HH};
    if (tid < 8) {
        float s = 0.f;
        for (int i = 0; i < 32; i++) s += g_partials[tid * 32 + i];
        aw[tid] = s / (float)szs[tid];
    }
    const float* bs[8] = {P.bii, P.bhi, P.bif, P.bhf, P.bio, P.bho, P.big, P.bhg};
    for (int v = 0; v < 8; v++) {
        float s = 0.f;
        for (int i = tid; i < HSZ; i += 256) s += fabsf(bs[v][i]);
        red[tid] = s;
        __syncthreads();
        for (int o = 128; o > 0; o >>= 1) {
            if (tid < o) red[tid] += red[tid + o];
            __syncthreads();
        }
        if (tid == 0) ab[v] = red[0] / (float)HSZ;
        __syncthreads();
    }
    if (tid < 4) {
        const int mx[4] = {0, 2, 6, 4};
        const int mh[4] = {1, 3, 7, 5};
        g_scalars[tid]     = aw[mx[tid]];
        g_scalars[4 + tid] = aw[mh[tid]];
    }
    __syncthreads();
    const float* bx[4] = {P.bii, P.bif, P.big, P.bio};
    const float* bh[4] = {P.bhi, P.bhf, P.bhg, P.bho};
    float abx[4] = {ab[0], ab[2], ab[6], ab[4]};
    float abh[4] = {ab[1], ab[3], ab[7], ab[5]};
    for (int c = tid; c < NC; c += 256) {
        int j = c >> 2, g = c & 3;
        g_bias[c] = abx[g] * sgnf(bx[g][j]) + abh[g] * sgnf(bh[g][j]);
    }
    for (int i = tid; i < 128 * 32; i += 256) g_arrive[i] = 0u;   // reset barrier flags
}

__global__ void k_binarize(Ptrs P) {
    const float* wx[4] = {P.wii, P.wif, P.wig, P.wio};
    const float* wh[4] = {P.whi, P.whf, P.whg, P.who};
    int idx = blockIdx.x * 256 + threadIdx.x;
    if (idx < NC * FSZ) {
        int c = idx >> 9, k = idx & 511;
        int j = c >> 2, g = c & 3;
        g_wx[idx] = __float2bfloat16(sgnf(wx[g][(size_t)j * FSZ + k]));
    } else {
        int r = idx - NC * FSZ;
        if (r < NC * HSZ) {
            int c = r >> 10, k = r & 1023;
            int j = c >> 2, g = c & 3;
            g_wh[r] = __float2bfloat16(sgnf(wh[g][(size_t)j * HSZ + k]));
        }
    }
}

__global__ void k_convx(Ptrs P) {
    int idx = blockIdx.x * 256 + threadIdx.x;
    if (idx < BSZ * SSZ * FSZ) {
        float v = P.x[idx];
        __nv_bfloat16 hi = __float2bfloat16(v);
        g_xhi[idx] = hi;
        g_xlo[idx] = __float2bfloat16(v - __bfloat162float(hi));
    }
}

__global__ void k_inith(Ptrs P) {
    int idx = blockIdx.x * 256 + threadIdx.x;
    if (idx < BSZ * HSZ) {
        float v = P.h0[idx];
        __nv_bfloat16 hi = __float2bfloat16(v);
        g_hhi[idx] = hi;
        g_hlo[idx] = __float2bfloat16(v - __bfloat162float(hi));
    }
}

// ---------------- input projection GEMM ----------------
// Block: 128 rows x 128 cols, K=512. Wx in padded smem (reused by whole block);
// A (hi/lo) via wmma global loads (L1-cached, reused across warps).
// Warp layout: wr in 0..3 (32-row tile), wc in 0..1 (64-col tile).
__global__ void __launch_bounds__(256) k_xproj() {
    extern __shared__ unsigned char smem[];
    __nv_bfloat16* sb = (__nv_bfloat16*)smem;   // 128 x XBP bf16 = 133,120 B
    int tid = threadIdx.x;
    int c0 = blockIdx.x * 128, row0 = blockIdx.y * 128;

    {   // stage Wx tile into padded layout (64 uint4 per 512-elem row)
        const uint4* src = (const uint4*)(g_wx + (size_t)c0 * FSZ);
        for (int i = tid; i < 8192; i += 256) {
            int r = i >> 6, cg = i & 63;
            *(uint4*)((unsigned char*)sb + r * (XBP * 2) + cg * 16) = src[i];
        }
    }
    __syncthreads();

    int wid = tid >> 5;
    int wr = wid >> 1, wc = wid & 1;

    wmma::fragment<wmma::accumulator, 16, 16, 16, float> cf[2][4];
#pragma unroll
    for (int fr = 0; fr < 2; fr++)
#pragma unroll
        for (int fc = 0; fc < 4; fc++) wmma::fill_fragment(cf[fr][fc], 0.f);

    wmma::fragment<wmma::matrix_a, 16, 16, 16, __nv_bfloat16, wmma::row_major> ahi[2], alo[2];
    wmma::fragment<wmma::matrix_b, 16, 16, 16, __nv_bfloat16, wmma::col_major> bf;

    const __nv_bfloat16* Ahi0 = g_xhi + (size_t)(row0 + wr * 32) * FSZ;
    const __nv_bfloat16* Alo0 = g_xlo + (size_t)(row0 + wr * 32) * FSZ;

#pragma unroll 2
    for (int k = 0; k < FSZ; k += 16) {
#pragma unroll
        for (int fr = 0; fr < 2; fr++) {
            wmma::load_matrix_sync(ahi[fr], Ahi0 + (size_t)(fr * 16) * FSZ + k, FSZ);
            wmma::load_matrix_sync(alo[fr], Alo0 + (size_t)(fr * 16) * FSZ + k, FSZ);
        }
#pragma unroll
        for (int fc = 0; fc < 4; fc++) {
            wmma::load_matrix_sync(bf, sb + (size_t)(wc * 64 + fc * 16) * XBP + k, XBP);
#pragma unroll
            for (int fr = 0; fr < 2; fr++) {
                wmma::mma_sync(cf[fr][fc], ahi[fr], bf, cf[fr][fc]);
                wmma::mma_sync(cf[fr][fc], alo[fr], bf, cf[fr][fc]);
            }
        }
    }
    __syncthreads();
    float* scf = (float*)smem;   // 128 x 132 f32 = 67,584 B (aliases sb)
#pragma unroll
    for (int fr = 0; fr < 2; fr++)
#pragma unroll
        for (int fc = 0; fc < 4; fc++)
            wmma::store_matrix_sync(scf + (wr * 32 + fr * 16) * 132 + wc * 64 + fc * 16,
                                    cf[fr][fc], 132, wmma::mem_row_major);
    __syncthreads();

    float4 ax = *(const float4*)&g_scalars[0];
    for (int i = tid; i < 128 * 32; i += 256) {
        int rl = i >> 5, q = i & 31;           // q indexes a float4 (4 cols)
        int r = row0 + rl;
        int b = r >> 9, t = r & 511;
        int c = c0 + q * 4;
        float4 v = *(float4*)&scf[rl * 132 + q * 4];
        float4 bb = *(const float4*)&g_bias[c];
        v.x = ax.x * v.x + bb.x;
        v.y = ax.y * v.y + bb.y;
        v.z = ax.z * v.z + bb.z;
        v.w = ax.w * v.w + bb.w;
        *(float4*)&g_xproj[((size_t)t * BSZ + b) * NC + c] = v;
    }
}

// ---------------- persistent recurrent kernel ----------------
// 128 blocks; block owns 32 interleaved gate-cols. Flag-array barrier,
// 2-chunk cp.async pipeline overlapping h staging with MMA.
__global__ void __launch_bounds__(256, 1) k_recur(const float* __restrict__ c0in,
                                                  float* __restrict__ out) {
    extern __shared__ unsigned char smem[];
    unsigned char* swb  = smem;                 // 32 x 2064 weights
    unsigned char* shhb = smem + 66048;         // 32 x 2064 h hi
    unsigned char* shlb = smem + 132096;        // 32 x 2064 h lo
    float*         sc   = (float*)(smem + 198144);   // 2 x 32 x SCP f32
    __nv_bfloat16* sw  = (__nv_bfloat16*)swb;
    __nv_bfloat16* shh = (__nv_bfloat16*)shhb;
    __nv_bfloat16* shl = (__nv_bfloat16*)shlb;

    int tid = threadIdx.x, bid = blockIdx.x;
    int ccol = bid * 32;

    {   // stage this block's Wh sign columns once
        const uint4* src = (const uint4*)(g_wh + (size_t)ccol * HSZ);
        for (int i = tid; i < 4096; i += 256) {
            int r = i >> 7, cg = i & 127;
            *(uint4*)(swb + r * 2064 + cg * 16) = src[i];
        }
    }
    float ah[4] = {g_scalars[4], g_scalars[5], g_scalars[6], g_scalars[7]};

    int b = tid >> 3, jl = tid & 7;
    int jg = bid * 8 + jl;
    float creg = c0in[b * HSZ + jg];

    int wid = tid >> 5;
    int ks = wid & 1, tile = wid >> 1;
    int tr = tile & 1, tc = tile >> 1;

    float* outh = out + (size_t)BSZ * SSZ * HSZ;
    float* outc = outh + BSZ * HSZ;

    int p = 0;
    for (int t = 0; t < SSZ; t++) {
        float4 xp = *(const float4*)(g_xproj + ((size_t)t * BSZ + b) * NC + ccol + jl * 4);

        // ---- stage h hi/lo, two K-chunks with separate commit groups ----
        const uint4* s1 = (const uint4*)(g_hhi + p * (BSZ * HSZ));
        const uint4* s2 = (const uint4*)(g_hlo + p * (BSZ * HSZ));
#pragma unroll 1
        for (int i = tid; i < 2048; i += 256) {       // chunk 0: K [0,512)
            int r = i >> 6, cg = i & 63;
            cp16(shhb + r * 2064 + cg * 16, s1 + r * 128 + cg);
            cp16(shlb + r * 2064 + cg * 16, s2 + r * 128 + cg);
        }
        cp_commit();
#pragma unroll 1
        for (int i = tid; i < 2048; i += 256) {       // chunk 1: K [512,1024)
            int r = i >> 6, cg = i & 63;
            cp16(shhb + r * 2064 + 1024 + cg * 16, s1 + r * 128 + 64 + cg);
            cp16(shlb + r * 2064 + 1024 + cg * 16, s2 + r * 128 + 64 + cg);
        }
        cp_commit();

        wmma::fragment<wmma::accumulator, 16, 16, 16, float> cfh, cfl;
        wmma::fill_fragment(cfh, 0.f);
        wmma::fill_fragment(cfl, 0.f);
        wmma::fragment<wmma::matrix_a, 16, 16, 16, __nv_bfloat16, wmma::row_major> ahi, alo;
        wmma::fragment<wmma::matrix_b, 16, 16, 16, __nv_bfloat16, wmma::col_major> bf;

        cp_wait1();        // chunk 0 landed
        __syncthreads();
#pragma unroll 4
        for (int kk = 0; kk < 256; kk += 16) {
            int k = ks * 256 + kk;
            wmma::load_matrix_sync(ahi, shh + (size_t)(tr * 16) * SWP + k, SWP);
            wmma::load_matrix_sync(alo, shl + (size_t)(tr * 16) * SWP + k, SWP);
            wmma::load_matrix_sync(bf, sw + (size_t)(tc * 16) * SWP + k, SWP);
            wmma::mma_sync(cfh, ahi, bf, cfh);
            wmma::mma_sync(cfl, alo, bf, cfl);
        }
        cp_wait0();        // chunk 1 landed
        __syncthreads();
#pragma unroll 4
        for (int kk = 0; kk < 256; kk += 16) {
            int k = 512 + ks * 256 + kk;
            wmma::load_matrix_sync(ahi, shh + (size_t)(tr * 16) * SWP + k, SWP);
            wmma::load_matrix_sync(alo, shl + (size_t)(tr * 16) * SWP + k, SWP);
            wmma::load_matrix_sync(bf, sw + (size_t)(tc * 16) * SWP + k, SWP);
            wmma::mma_sync(cfh, ahi, bf, cfh);
            wmma::mma_sync(cfl, alo, bf, cfl);
        }
#pragma unroll
        for (int e = 0; e < cfh.num_elements; e++) cfh.x[e] += cfl.x[e];
        wmma::store_matrix_sync(sc + ks * (32 * SCP) + (tr * 16) * SCP + tc * 16, cfh, SCP,
                                wmma::mem_row_major);
        __syncthreads();

        // ---- epilogue: one thread per (b, j) ----
        int ci = b * SCP + jl * 4;
        int o2 = 32 * SCP;
        float pi = xp.x + ah[0] * (sc[ci + 0] + sc[o2 + ci + 0]);
        float pf = xp.y + ah[1] * (sc[ci + 1] + sc[o2 + ci + 1]);
        float pg = xp.z + ah[2] * (sc[ci + 2] + sc[o2 + ci + 2]);
        float po = xp.w + ah[3] * (sc[ci + 3] + sc[o2 + ci + 3]);
        float gi = 1.f / (1.f + expf(-pi));
        float gf = 1.f / (1.f + expf(-pf));
        float gg = tanhf(pg);
        float go = 1.f / (1.f + expf(-po));
        creg = gf * creg + gi * gg;
        float h2 = go * tanhf(creg);

        out[((size_t)b * SSZ + t) * HSZ + jg] = h2;
        int np = p ^ 1;
        __nv_bfloat16 hi = __float2bfloat16(h2);
        g_hhi[np * (BSZ * HSZ) + b * HSZ + jg] = hi;
        g_hlo[np * (BSZ * HSZ) + b * HSZ + jg] =
            __float2bfloat16(h2 - __bfloat162float(hi));
        if (t == SSZ - 1) {
            outh[b * HSZ + jg] = h2;
            outc[b * HSZ + jg] = creg;
        }

        // ---- flag-array barrier ----
        __threadfence();
        __syncthreads();
        if (tid == 0) st_rel(&g_arrive[bid * 32], (unsigned)(t + 1));
        if (tid < 128) {
            const unsigned* f = &g_arrive[tid * 32];
            unsigned spins = 0;
            while (ld_acq(f) < (unsigned)(t + 1)) {
                if (++spins > (1u << 13)) break;   // fail-slow, not hang
            }
        }
        __syncthreads();
        p = np;
    }
}

// ---------------- launcher ----------------
extern "C" void kernel_launch(void* const* d_in, const int* in_sizes, int n_in,
                              void* d_out, int out_size) {
    Ptrs P;
    P.x   = (const float*)d_in[0];
    P.h0  = (const float*)d_in[1];
    P.c0  = (const float*)d_in[2];
    P.wii = (const float*)d_in[3];  P.whi = (const float*)d_in[4];
    P.bii = (const float*)d_in[5];  P.bhi = (const float*)d_in[6];
    P.wif = (const float*)d_in[7];  P.whf = (const float*)d_in[8];
    P.bif = (const float*)d_in[9];  P.bhf = (const float*)d_in[10];
    P.wio = (const float*)d_in[11]; P.who = (const float*)d_in[12];
    P.bio = (const float*)d_in[13]; P.bho = (const float*)d_in[14];
    P.wig = (const float*)d_in[15]; P.whg = (const float*)d_in[16];
    P.big = (const float*)d_in[17]; P.bhg = (const float*)d_in[18];

    cudaFuncSetAttribute(k_xproj, cudaFuncAttributeMaxDynamicSharedMemorySize, 133120);
    cudaFuncSetAttribute(k_recur, cudaFuncAttributeMaxDynamicSharedMemorySize, 207360);

    k_reduce<<<256, 256>>>(P);
    k_finalize<<<1, 256>>>(P);
    k_binarize<<<24576, 256>>>(P);
    k_convx<<<32768, 256>>>(P);
    k_inith<<<128, 256>>>(P);
    k_xproj<<<dim3(32, 128), 256, 133120>>>();
    k_recur<<<128, 256, 207360>>>((const float*)d_in[2], (float*)d_out);
}

// round 5
// speedup vs baseline: 3.2528x; 1.2642x over previous
#include <cuda_runtime.h>
#include <cuda_bf16.h>
#include <mma.h>
#include <cstdint>
#include <cstddef>

using namespace nvcuda;

// Problem dims
#define BSZ 32
#define SSZ 512
#define FSZ 512
#define HSZ 1024
#define NC  4096   // 4 gates * H, interleaved as c = j*4 + g  (g: 0=i,1=f,2=g,3=o)

constexpr int HF = HSZ * FSZ;
constexpr int HH = HSZ * HSZ;

// Padded strides: row_stride_bytes mod 128 == 16 -> conflict-free LDSM.
#define SWP  1032          // K=1024 row, elements (2064 B)
#define SWPB 2064          // bytes
#define XBP  520           // K=512 row (xproj)
#define SCP  68            // f32 partial stride (272 B)

// Recurrent grid: 2 batch-groups x 64 col-blocks.
#define NGRP 2
#define NCB  64            // col blocks per group
#define BPG  16            // batches per group
#define CPB  64            // gate-cols per block

// smem offsets (k_recur)
#define SM_W    0                       // 64 x 2064 = 132096
#define SM_HH   132096                  // 16 x 2064 = 33024
#define SM_HL   165120                  // 16 x 2064 = 33024
#define SM_SC   198144                  // 2 x 16 x 68 x 4 = 8704
#define SM_MBAR 206848                  // 8
#define SM_TOT  206912

// ---------------- device scratch ----------------
__device__ float          g_partials[256];
__device__ float          g_scalars[8];                    // [0..3] alpha_x, [4..7] alpha_h
__device__ float          g_bias[NC];
__device__ __nv_bfloat16  g_wx[(size_t)NC * FSZ];          // sign(Wx) (xproj)
__device__ __nv_bfloat16  g_whp[(size_t)NC * SWP];         // sign(Wh), PADDED rows
__device__ __nv_bfloat16  g_xhi[(size_t)BSZ * SSZ * FSZ];
__device__ __nv_bfloat16  g_xlo[(size_t)BSZ * SSZ * FSZ];
__device__ float          g_xproj[(size_t)SSZ * BSZ * NC];
__device__ __nv_bfloat16  g_hhp[2 * BSZ * SWP];            // h hi, padded, double-buffered
__device__ __nv_bfloat16  g_hlp[2 * BSZ * SWP];            // h lo, padded
__device__ unsigned       g_arrive[128 * 32];              // flags, 128B apart

struct Ptrs {
    const float *x, *h0, *c0,
        *wii, *whi, *bii, *bhi,
        *wif, *whf, *bif, *bhf,
        *wio, *who, *bio, *bho,
        *wig, *whg, *big, *bhg;
};

__device__ __forceinline__ float sgnf(float v) {
    return (v > 0.f) ? 1.f : ((v < 0.f) ? -1.f : 0.f);
}
__device__ __forceinline__ unsigned ld_acq(const unsigned* p) {
    unsigned v;
    asm volatile("ld.acquire.gpu.global.u32 %0, [%1];" : "=r"(v) : "l"(p));
    return v;
}
__device__ __forceinline__ void st_rel(unsigned* p, unsigned v) {
    asm volatile("st.release.gpu.global.u32 [%0], %1;" :: "l"(p), "r"(v));
}
__device__ __forceinline__ void mbar_init(unsigned mbar, unsigned cnt) {
    asm volatile("mbarrier.init.shared.b64 [%0], %1;" :: "r"(mbar), "r"(cnt) : "memory");
}
__device__ __forceinline__ void mbar_expect(unsigned mbar, unsigned bytes) {
    asm volatile("mbarrier.arrive.expect_tx.shared.b64 _, [%0], %1;"
                 :: "r"(mbar), "r"(bytes) : "memory");
}
__device__ __forceinline__ void bulk_g2s(unsigned dst, const void* src, unsigned bytes,
                                         unsigned mbar) {
    asm volatile(
        "cp.async.bulk.shared::cta.global.mbarrier::complete_tx::bytes [%0], [%1], %2, [%3];"
        :: "r"(dst), "l"(src), "r"(bytes), "r"(mbar) : "memory");
}
__device__ __forceinline__ void mbar_wait(unsigned mbar, unsigned parity) {
    unsigned done;
    asm volatile(
        "{\n\t.reg .pred p;\n\t"
        "mbarrier.try_wait.parity.shared.b64 p, [%1], %2;\n\t"
        "selp.b32 %0, 1, 0, p;\n\t}"
        : "=r"(done) : "r"(mbar), "r"(parity) : "memory");
    unsigned spins = 0;
    while (!done) {
        asm volatile(
            "{\n\t.reg .pred p;\n\t"
            "mbarrier.try_wait.parity.shared.b64 p, [%1], %2;\n\t"
            "selp.b32 %0, 1, 0, p;\n\t}"
            : "=r"(done) : "r"(mbar), "r"(parity) : "memory");
        if (++spins > (1u << 20)) break;   // fail-slow, never hang
    }
}

// ---------------- setup kernels ----------------
__global__ void k_reduce(Ptrs P) {
    const float* ws[8] = {P.wii, P.whi, P.wif, P.whf, P.wio, P.who, P.wig, P.whg};
    const int    szs[8] = {HF, HH, HF, HH, HF, HH, HF, HH};
    int m = blockIdx.x >> 5, sl = blockIdx.x & 31;
    int per = szs[m] / 32;
    const float* w = ws[m] + (size_t)sl * per;
    float s = 0.f;
    for (int i = threadIdx.x; i < per; i += 256) s += fabsf(w[i]);
    __shared__ float red[256];
    red[threadIdx.x] = s;
    __syncthreads();
    for (int o = 128; o > 0; o >>= 1) {
        if (threadIdx.x < o) red[threadIdx.x] += red[threadIdx.x + o];
        __syncthreads();
    }
    if (threadIdx.x == 0) g_partials[m * 32 + sl] = red[0];
}

__global__ void k_finalize(Ptrs P) {
    int tid = threadIdx.x;
    __shared__ float red[256];
    __shared__ float aw[8], ab[8];
    const int szs[8] = {HF, HH, HF, HH, HF, HH, HF, HH};
    if (tid < 8) {
        float s = 0.f;
        for (int i = 0; i < 32; i++) s += g_partials[tid * 32 + i];
        aw[tid] = s / (float)szs[tid];
    }
    const float* bs[8] = {P.bii, P.bhi, P.bif, P.bhf, P.bio, P.bho, P.big, P.bhg};
    for (int v = 0; v < 8; v++) {
        float s = 0.f;
        for (int i = tid; i < HSZ; i += 256) s += fabsf(bs[v][i]);
        red[tid] = s;
        __syncthreads();
        for (int o = 128; o > 0; o >>= 1) {
            if (tid < o) red[tid] += red[tid + o];
            __syncthreads();
        }
        if (tid == 0) ab[v] = red[0] / (float)HSZ;
        __syncthreads();
    }
    if (tid < 4) {
        const int mx[4] = {0, 2, 6, 4};
        const int mh[4] = {1, 3, 7, 5};
        g_scalars[tid]     = aw[mx[tid]];
        g_scalars[4 + tid] = aw[mh[tid]];
    }
    __syncthreads();
    const float* bx[4] = {P.bii, P.bif, P.big, P.bio};
    const float* bh[4] = {P.bhi, P.bhf, P.bhg, P.bho};
    float abx[4] = {ab[0], ab[2], ab[6], ab[4]};
    float abh[4] = {ab[1], ab[3], ab[7], ab[5]};
    for (int c = tid; c < NC; c += 256) {
        int j = c >> 2, g = c & 3;
        g_bias[c] = abx[g] * sgnf(bx[g][j]) + abh[g] * sgnf(bh[g][j]);
    }
    for (int i = tid; i < 128 * 32; i += 256) g_arrive[i] = 0u;
}

__global__ void k_binarize(Ptrs P) {
    const float* wx[4] = {P.wii, P.wif, P.wig, P.wio};
    const float* wh[4] = {P.whi, P.whf, P.whg, P.who};
    int idx = blockIdx.x * 256 + threadIdx.x;
    if (idx < NC * FSZ) {
        int c = idx >> 9, k = idx & 511;
        int j = c >> 2, g = c & 3;
        g_wx[idx] = __float2bfloat16(sgnf(wx[g][(size_t)j * FSZ + k]));
    } else {
        int r = idx - NC * FSZ;
        if (r < NC * HSZ) {
            int c = r >> 10, k = r & 1023;
            int j = c >> 2, g = c & 3;
            g_whp[(size_t)c * SWP + k] = __float2bfloat16(sgnf(wh[g][(size_t)j * HSZ + k]));
        }
    }
}

__global__ void k_convx(Ptrs P) {
    int idx = blockIdx.x * 256 + threadIdx.x;
    if (idx < BSZ * SSZ * FSZ) {
        float v = P.x[idx];
        __nv_bfloat16 hi = __float2bfloat16(v);
        g_xhi[idx] = hi;
        g_xlo[idx] = __float2bfloat16(v - __bfloat162float(hi));
    }
}

__global__ void k_inith(Ptrs P) {
    int idx = blockIdx.x * 256 + threadIdx.x;
    if (idx < BSZ * HSZ) {
        int b = idx >> 10, k = idx & 1023;
        float v = P.h0[idx];
        __nv_bfloat16 hi = __float2bfloat16(v);
        g_hhp[(size_t)b * SWP + k] = hi;     // parity 0
        g_hlp[(size_t)b * SWP + k] = __float2bfloat16(v - __bfloat162float(hi));
    }
}

// ---------------- input projection GEMM (unchanged structure) ----------------
__global__ void __launch_bounds__(256) k_xproj() {
    extern __shared__ unsigned char smem[];
    __nv_bfloat16* sb = (__nv_bfloat16*)smem;   // 128 x XBP bf16
    int tid = threadIdx.x;
    int c0 = blockIdx.x * 128, row0 = blockIdx.y * 128;

    {
        const uint4* src = (const uint4*)(g_wx + (size_t)c0 * FSZ);
        for (int i = tid; i < 8192; i += 256) {
            int r = i >> 6, cg = i & 63;
            *(uint4*)((unsigned char*)sb + r * (XBP * 2) + cg * 16) = src[i];
        }
    }
    __syncthreads();

    int wid = tid >> 5;
    int wr = wid >> 1, wc = wid & 1;

    wmma::fragment<wmma::accumulator, 16, 16, 16, float> cf[2][4];
#pragma unroll
    for (int fr = 0; fr < 2; fr++)
#pragma unroll
        for (int fc = 0; fc < 4; fc++) wmma::fill_fragment(cf[fr][fc], 0.f);

    wmma::fragment<wmma::matrix_a, 16, 16, 16, __nv_bfloat16, wmma::row_major> ahi[2], alo[2];
    wmma::fragment<wmma::matrix_b, 16, 16, 16, __nv_bfloat16, wmma::col_major> bf;

    const __nv_bfloat16* Ahi0 = g_xhi + (size_t)(row0 + wr * 32) * FSZ;
    const __nv_bfloat16* Alo0 = g_xlo + (size_t)(row0 + wr * 32) * FSZ;

#pragma unroll 2
    for (int k = 0; k < FSZ; k += 16) {
#pragma unroll
        for (int fr = 0; fr < 2; fr++) {
            wmma::load_matrix_sync(ahi[fr], Ahi0 + (size_t)(fr * 16) * FSZ + k, FSZ);
            wmma::load_matrix_sync(alo[fr], Alo0 + (size_t)(fr * 16) * FSZ + k, FSZ);
        }
#pragma unroll
        for (int fc = 0; fc < 4; fc++) {
            wmma::load_matrix_sync(bf, sb + (size_t)(wc * 64 + fc * 16) * XBP + k, XBP);
#pragma unroll
            for (int fr = 0; fr < 2; fr++) {
                wmma::mma_sync(cf[fr][fc], ahi[fr], bf, cf[fr][fc]);
                wmma::mma_sync(cf[fr][fc], alo[fr], bf, cf[fr][fc]);
            }
        }
    }
    __syncthreads();
    float* scf = (float*)smem;
#pragma unroll
    for (int fr = 0; fr < 2; fr++)
#pragma unroll
        for (int fc = 0; fc < 4; fc++)
            wmma::store_matrix_sync(scf + (wr * 32 + fr * 16) * 132 + wc * 64 + fc * 16,
                                    cf[fr][fc], 132, wmma::mem_row_major);
    __syncthreads();

    float4 ax = *(const float4*)&g_scalars[0];
    for (int i = tid; i < 128 * 32; i += 256) {
        int rl = i >> 5, q = i & 31;
        int r = row0 + rl;
        int b = r >> 9, t = r & 511;
        int c = c0 + q * 4;
        float4 v = *(float4*)&scf[rl * 132 + q * 4];
        float4 bb = *(const float4*)&g_bias[c];
        v.x = ax.x * v.x + bb.x;
        v.y = ax.y * v.y + bb.y;
        v.z = ax.z * v.z + bb.z;
        v.w = ax.w * v.w + bb.w;
        *(float4*)&g_xproj[((size_t)t * BSZ + b) * NC + c] = v;
    }
}

// ---------------- persistent recurrent kernel ----------------
// 128 blocks = 2 batch-groups x 64 col-blocks. Each block: 16 batches x 64 gate-cols.
// Wh (64 x 2064B) resident in smem; h staged via cp.async.bulk from padded global.
__global__ void __launch_bounds__(256, 1) k_recur(const float* __restrict__ c0in,
                                                  float* __restrict__ out) {
    extern __shared__ unsigned char smem[];
    __nv_bfloat16* sw  = (__nv_bfloat16*)(smem + SM_W);
    __nv_bfloat16* shh = (__nv_bfloat16*)(smem + SM_HH);
    __nv_bfloat16* shl = (__nv_bfloat16*)(smem + SM_HL);
    float*         sc  = (float*)(smem + SM_SC);
    unsigned smem_base = (unsigned)__cvta_generic_to_shared(smem);
    unsigned mbar = smem_base + SM_MBAR;

    int tid = threadIdx.x, bid = blockIdx.x;
    int group = bid >> 6, colb = bid & 63;
    int ccol = colb * CPB;                    // first gate-col
    int j0 = ccol >> 2;                       // first j

    if (tid == 0) mbar_init(mbar, 1);
    __syncthreads();

    // t=0: stage weights + initial h in one mbarrier phase
    if (tid == 0) {
        mbar_expect(mbar, 64 * SWPB + 2 * BPG * SWPB);
        bulk_g2s(smem_base + SM_W, g_whp + (size_t)ccol * SWP, 64 * SWPB, mbar);
        bulk_g2s(smem_base + SM_HH, g_hhp + (size_t)(group * BPG) * SWP, BPG * SWPB, mbar);
        bulk_g2s(smem_base + SM_HL, g_hlp + (size_t)(group * BPG) * SWP, BPG * SWPB, mbar);
    }

    float ah[4] = {g_scalars[4], g_scalars[5], g_scalars[6], g_scalars[7]};

    int b = tid >> 4, jl = tid & 15;          // thread owns (local batch, local j)
    int bg = group * BPG + b;                 // global batch
    int jg = j0 + jl;                         // global j
    float creg = c0in[bg * HSZ + jg];

    int wid = tid >> 5;
    int wc = wid & 3, ks = wid >> 2;          // 4 col-tiles x 2-way K split

    float* outh = out + (size_t)BSZ * SSZ * HSZ;
    float* outc = outh + BSZ * HSZ;

    const unsigned* myflags = &g_arrive[(group * 64) * 32];

    for (int t = 0; t < SSZ; t++) {
        float4 xp = *(const float4*)(g_xproj + ((size_t)t * BSZ + bg) * NC + ccol + jl * 4);

        mbar_wait(mbar, (unsigned)(t & 1));
        __syncthreads();

        wmma::fragment<wmma::accumulator, 16, 16, 16, float> cfh, cfl;
        wmma::fill_fragment(cfh, 0.f);
        wmma::fill_fragment(cfl, 0.f);
        wmma::fragment<wmma::matrix_a, 16, 16, 16, __nv_bfloat16, wmma::row_major> ahi, alo;
        wmma::fragment<wmma::matrix_b, 16, 16, 16, __nv_bfloat16, wmma::col_major> bf;

#pragma unroll 4
        for (int kk = 0; kk < 512; kk += 16) {
            int k = ks * 512 + kk;
            wmma::load_matrix_sync(ahi, shh + k, SWP);
            wmma::load_matrix_sync(alo, shl + k, SWP);
            wmma::load_matrix_sync(bf, sw + (size_t)(wc * 16) * SWP + k, SWP);
            wmma::mma_sync(cfh, ahi, bf, cfh);
            wmma::mma_sync(cfl, alo, bf, cfl);
        }
#pragma unroll
        for (int e = 0; e < cfh.num_elements; e++) cfh.x[e] += cfl.x[e];
        wmma::store_matrix_sync(sc + ks * (16 * SCP) + wc * 16, cfh, SCP,
                                wmma::mem_row_major);
        __syncthreads();

        // ---- epilogue: one thread per (b, j) ----
        int ci = b * SCP + jl * 4;
        int o2 = 16 * SCP;
        float pi = xp.x + ah[0] * (sc[ci + 0] + sc[o2 + ci + 0]);
        float pf = xp.y + ah[1] * (sc[ci + 1] + sc[o2 + ci + 1]);
        float pg = xp.z + ah[2] * (sc[ci + 2] + sc[o2 + ci + 2]);
        float po = xp.w + ah[3] * (sc[ci + 3] + sc[o2 + ci + 3]);
        float gi = 1.f / (1.f + expf(-pi));
        float gf = 1.f / (1.f + expf(-pf));
        float gg = tanhf(pg);
        float go = 1.f / (1.f + expf(-po));
        creg = gf * creg + gi * gg;
        float h2 = go * tanhf(creg);

        // publish h (padded layout), then release flag — minimal critical path
        int np = (t + 1) & 1;
        __nv_bfloat16 hi = __float2bfloat16(h2);
        g_hhp[(size_t)(np * BSZ + bg) * SWP + jg] = hi;
        g_hlp[(size_t)(np * BSZ + bg) * SWP + jg] =
            __float2bfloat16(h2 - __bfloat162float(hi));

        __threadfence();
        __syncthreads();
        if (tid == 0) st_rel(&g_arrive[bid * 32], (unsigned)(t + 1));

        // off-critical-path output stores
        out[((size_t)bg * SSZ + t) * HSZ + jg] = h2;
        if (t == SSZ - 1) {
            outh[bg * HSZ + jg] = h2;
            outc[bg * HSZ + jg] = creg;
        }

        // wait for this group's 64 blocks
        if (tid < 64) {
            const unsigned* f = &myflags[tid * 32];
            unsigned spins = 0;
            while (ld_acq(f) < (unsigned)(t + 1)) {
                if (++spins > (1u << 14)) break;   // fail-slow
            }
        }
        __syncthreads();

        // kick next step's h staging (reads are ordered after flag acquire)
        if (t < SSZ - 1 && tid == 0) {
            mbar_expect(mbar, 2 * BPG * SWPB);
            bulk_g2s(smem_base + SM_HH, g_hhp + (size_t)(np * BSZ + group * BPG) * SWP,
                     BPG * SWPB, mbar);
            bulk_g2s(smem_base + SM_HL, g_hlp + (size_t)(np * BSZ + group * BPG) * SWP,
                     BPG * SWPB, mbar);
        }
    }
}

// ---------------- launcher ----------------
extern "C" void kernel_launch(void* const* d_in, const int* in_sizes, int n_in,
                              void* d_out, int out_size) {
    Ptrs P;
    P.x   = (const float*)d_in[0];
    P.h0  = (const float*)d_in[1];
    P.c0  = (const float*)d_in[2];
    P.wii = (const float*)d_in[3];  P.whi = (const float*)d_in[4];
    P.bii = (const float*)d_in[5];  P.bhi = (const float*)d_in[6];
    P.wif = (const float*)d_in[7];  P.whf = (const float*)d_in[8];
    P.bif = (const float*)d_in[9];  P.bhf = (const float*)d_in[10];
    P.wio = (const float*)d_in[11]; P.who = (const float*)d_in[12];
    P.bio = (const float*)d_in[13]; P.bho = (const float*)d_in[14];
    P.wig = (const float*)d_in[15]; P.whg = (const float*)d_in[16];
    P.big = (const float*)d_in[17]; P.bhg = (const float*)d_in[18];

    cudaFuncSetAttribute(k_xproj, cudaFuncAttributeMaxDynamicSharedMemorySize, 133120);
    cudaFuncSetAttribute(k_recur, cudaFuncAttributeMaxDynamicSharedMemorySize, SM_TOT);

    k_reduce<<<256, 256>>>(P);
    k_finalize<<<1, 256>>>(P);
    k_binarize<<<24576, 256>>>(P);
    k_convx<<<32768, 256>>>(P);
    k_inith<<<128, 256>>>(P);
    k_xproj<<<dim3(32, 128), 256, 133120>>>();
    k_recur<<<128, 256, SM_TOT>>>((const float*)d_in[2], (float*)d_out);
}